// round 9
// baseline (speedup 1.0000x reference)
#include <cuda_runtime.h>
#include <cuda_bf16.h>
#include <cuda_fp16.h>

#define NN 100000
#define NE 3200000
#define HID 36
#define NH 3
#define HD 12
#define FEH 48           // fp16 feat row stride in halves: 36 feat + pad = 96B
#define ESRC_CAP (NE + 5 * NN + 64)
#define FULL 0xffffffffu

// ---- persistent scratch ----
__device__ __align__(128) __half g_fe[(NN + 1) * FEH]; // row NN = zero pad row
__device__ float4 g_el4[NN + 1];     // el per node (+ pad row = -300)
__device__ float4 g_er4[NN];
__device__ float4 g_den4[NN];        // per-node softmax denominators
__device__ float  g_rst[NN * HID];   // x + bias (+ msg added by gather)
__device__ __align__(16) float4 g_erec[ESRC_CAP];  // {src_bits, w0, w1, w2}
__device__ int   g_deg[NN];          // zero-init; out_proj re-zeroes
__device__ int   g_off[NN];
__device__ int   g_end[NN];          // padded end (multiple of 6)
__device__ int   g_cursor[NN];
__device__ int   g_esrc[ESRC_CAP];
__device__ int   g_total;            // zero-init; out_proj re-zeroes

__device__ __forceinline__ unsigned pack2(float a, float b) {
    __half2 h = __floats2half2_rn(a, b);
    return *reinterpret_cast<unsigned*>(&h);
}
__device__ __forceinline__ unsigned long long f32x2_pack(float lo, float hi) {
    unsigned long long r;
    asm("mov.b64 %0, {%1, %2};" : "=l"(r) : "f"(lo), "f"(hi));
    return r;
}
__device__ __forceinline__ unsigned long long f32x2_fma(unsigned long long a,
                                                        unsigned long long b,
                                                        unsigned long long c) {
    unsigned long long d;
    asm("fma.rn.f32x2 %0, %1, %2, %3;" : "=l"(d) : "l"(a), "l"(b), "l"(c));
    return d;
}
__device__ __forceinline__ void f32x2_unpack(unsigned long long v, float& lo, float& hi) {
    asm("mov.b64 {%0, %1}, %2;" : "=f"(lo), "=f"(hi) : "l"(v));
}

// ============================================================================
// Launch 0: fused node_prep<layer0> (blocks [0,np_blocks)) + hist (rest).
// ============================================================================
__global__ __launch_bounds__(256)
void prep0_hist(const float* __restrict__ in,
                const float* __restrict__ lin0_w, const float* __restrict__ lin0_b,
                const float* __restrict__ fc_w,
                const float* __restrict__ a_l, const float* __restrict__ a_r,
                const float* __restrict__ bias,
                const int* __restrict__ dst,
                int n_nodes, int ne, int np_blocks) {
    if (blockIdx.x >= np_blocks) {
        int bid = blockIdx.x - np_blocks;
        int nb  = gridDim.x - np_blocks;
        int tid = bid * 256 + threadIdx.x;
        int stride = nb * 256;
        int nv = ne >> 2;
        const int4* d4 = reinterpret_cast<const int4*>(dst);
        for (int i = tid; i < nv; i += stride) {
            int4 d = __ldg(&d4[i]);
            atomicAdd(&g_deg[d.x], 1);
            atomicAdd(&g_deg[d.y], 1);
            atomicAdd(&g_deg[d.z], 1);
            atomicAdd(&g_deg[d.w], 1);
        }
        for (int i = (nv << 2) + tid; i < ne; i += stride)
            atomicAdd(&g_deg[dst[i]], 1);
        return;
    }

    __shared__ float sW[HID * HID];
    __shared__ float sW0[HID * HID];
    __shared__ float sAl[HID], sAr[HID], sB[HID], sB0[HID];

    int tid = threadIdx.x;
    for (int i = tid; i < HID * HID; i += 256) {
        sW[i]  = fc_w[i];
        sW0[i] = lin0_w[i];
    }
    if (tid < HID) {
        sAl[tid] = a_l[tid];
        sAr[tid] = a_r[tid];
        sB[tid]  = bias[tid];
        sB0[tid] = lin0_b[tid];
    }
    __syncthreads();

    int n = blockIdx.x * 256 + tid;
    if (n >= n_nodes) return;

    float nf[HID], x[HID];
#pragma unroll
    for (int k = 0; k < HID; k++) nf[k] = in[n * HID + k];
#pragma unroll
    for (int j = 0; j < HID; j++) {
        float a = sB0[j];
#pragma unroll
        for (int k = 0; k < HID; k++) a += nf[k] * sW0[k * HID + j];
        x[j] = a;
    }

    float f[HID];
#pragma unroll
    for (int j = 0; j < HID; j++) {
        float a = 0.f;
#pragma unroll
        for (int k = 0; k < HID; k++) a += x[k] * sW[k * HID + j];
        f[j] = a;
    }

#pragma unroll
    for (int j = 0; j < HID; j++)
        g_rst[n * HID + j] = x[j] + sB[j];

    float el[NH], er[NH];
#pragma unroll
    for (int h = 0; h < NH; h++) {
        float l = 0.f, r = 0.f;
#pragma unroll
        for (int d = 0; d < HD; d++) {
            l += f[h * HD + d] * sAl[h * HD + d];
            r += f[h * HD + d] * sAr[h * HD + d];
        }
        el[h] = l;
        er[h] = r;
    }
    g_el4[n] = make_float4(el[0], el[1], el[2], 0.f);
    g_er4[n] = make_float4(er[0], er[1], er[2], 0.f);

    unsigned u[20];
#pragma unroll
    for (int i = 0; i < 18; i++) u[i] = pack2(f[2 * i], f[2 * i + 1]);
    u[18] = 0;
    u[19] = 0;
    uint4* dp = reinterpret_cast<uint4*>(g_fe + n * FEH);
#pragma unroll
    for (int i = 0; i < 5; i++)
        dp[i] = make_uint4(u[4 * i], u[4 * i + 1], u[4 * i + 2], u[4 * i + 3]);
}

// ============================================================================
// Launch 1: single-pass scan over PADDED degrees (ceil to multiple of 6);
// fills pad slots with src = NN (zero node). Sets pad node's el row.
// ============================================================================
__global__ __launch_bounds__(256)
void scan_fused(int n) {
    __shared__ int sh[256];
    __shared__ int sbase;
    int t = threadIdx.x;
    int i = blockIdx.x * 256 + t;
    int deg = (i < n) ? g_deg[i] : 0;
    int pd = ((deg + 5) / 6) * 6;
    sh[t] = pd;
    __syncthreads();
    for (int d = 1; d < 256; d <<= 1) {
        int x = (t >= d) ? sh[t - d] : 0;
        __syncthreads();
        sh[t] += x;
        __syncthreads();
    }
    int incl = sh[t];
    if (t == 255) sbase = atomicAdd(&g_total, incl);
    __syncthreads();
    if (i < n) {
        int off = sbase + incl - pd;
        g_off[i] = off;
        g_end[i] = off + pd;
        g_cursor[i] = off;
        for (int j = off + deg; j < off + pd; j++)
            g_esrc[j] = NN;                 // pad slots -> zero node
    }
    if (blockIdx.x == 0 && t == 0)
        g_el4[NN] = make_float4(-300.f, -300.f, -300.f, 0.f); // exp -> 0
}

// ============================================================================
// Launch 2: scatter src into CSR slots
// ============================================================================
__global__ __launch_bounds__(256)
void scatter(const int* __restrict__ src, const int* __restrict__ dst, int ne) {
    int tid = blockIdx.x * blockDim.x + threadIdx.x;
    int stride = gridDim.x * blockDim.x;
    int nv = ne >> 2;
    const int4* s4 = reinterpret_cast<const int4*>(src);
    const int4* d4 = reinterpret_cast<const int4*>(dst);
    for (int i = tid; i < nv; i += stride) {
        int4 s = __ldg(&s4[i]);
        int4 d = __ldg(&d4[i]);
        int p0 = atomicAdd(&g_cursor[d.x], 1);
        int p1 = atomicAdd(&g_cursor[d.y], 1);
        int p2 = atomicAdd(&g_cursor[d.z], 1);
        int p3 = atomicAdd(&g_cursor[d.w], 1);
        g_esrc[p0] = s.x;
        g_esrc[p1] = s.y;
        g_esrc[p2] = s.z;
        g_esrc[p3] = s.w;
    }
    for (int i = (nv << 2) + tid; i < ne; i += stride) {
        int pos = atomicAdd(&g_cursor[dst[i]], 1);
        g_esrc[pos] = src[i];
    }
}

// ============================================================================
// Per-layer pass 1: edge weights. One warp per dst node, one lane per edge.
// w[h] = exp(leaky(el[src][h] + er[dst][h])). Writes {src,w0,w1,w2} records
// (coalesced) and the per-node denominator (in-register warp reduction).
// ============================================================================
__global__ __launch_bounds__(256)
void edge_w(int n_nodes) {
    int warp = (blockIdx.x * blockDim.x + threadIdx.x) >> 5;
    if (warp >= n_nodes) return;
    int lane = threadIdx.x & 31;
    int n = warp;

    int beg = g_off[n];
    int end = g_end[n];
    float4 er = g_er4[n];

    float d0 = 0.f, d1 = 0.f, d2 = 0.f;
    for (int j = beg + lane; j < end; j += 32) {
        int s = __ldg(&g_esrc[j]);
        float4 el = __ldg(&g_el4[s]);
        float v0 = el.x + er.x;
        float v1 = el.y + er.y;
        float v2 = el.z + er.z;
        v0 = v0 >= 0.f ? v0 : 0.2f * v0;
        v1 = v1 >= 0.f ? v1 : 0.2f * v1;
        v2 = v2 >= 0.f ? v2 : 0.2f * v2;
        float w0 = __expf(v0);
        float w1 = __expf(v1);
        float w2 = __expf(v2);
        d0 += w0; d1 += w1; d2 += w2;
        g_erec[j] = make_float4(__int_as_float(s), w0, w1, w2);
    }
#pragma unroll
    for (int o = 16; o > 0; o >>= 1) {
        d0 += __shfl_xor_sync(FULL, d0, o);
        d1 += __shfl_xor_sync(FULL, d1, o);
        d2 += __shfl_xor_sync(FULL, d2, o);
    }
    if (lane == 0) g_den4[n] = make_float4(d0, d1, d2, 0.f);
}

// ============================================================================
// Per-layer pass 2: gather-aggregate. One warp per node, 6 edges/iter,
// lane = e*5 + c. Loop body: rec broadcast load + feat chunk load + 4 fma2.
// No exp / shfl / branches in the loop.
// ============================================================================
__global__ __launch_bounds__(256)
void gather_agg(int n_nodes) {
    int warp = (blockIdx.x * blockDim.x + threadIdx.x) >> 5;
    if (warp >= n_nodes) return;
    int lane = threadIdx.x & 31;
    int n = warp;

    int e = lane / 5;        // 0..5 valid; 6 for lanes 30,31
    int c = lane - e * 5;    // 0..4
    bool laneOk = lane < 30;
    int esafe = laneOk ? e : 0;

    int ha = (c < 2) ? 0 : (c == 2 ? 1 : 2);
    int hb = (c == 0) ? 0 : (c < 3 ? 1 : 2);
    bool maskB = (c == 4);   // chunk 4 upper halves are pad

    int beg = g_off[n];
    int end = g_end[n];      // multiple of 6 past beg

    unsigned long long a01 = 0, a23 = 0, a45 = 0, a67 = 0;

    for (int i = beg; i < end; i += 6) {
        uint4 rec = __ldg(reinterpret_cast<const uint4*>(&g_erec[i + esafe]));
        int s = laneOk ? (int)rec.x : NN;
        uint4 q = __ldg(reinterpret_cast<const uint4*>(g_fe + s * FEH) + c);

        float w0 = __uint_as_float(rec.y);
        float w1 = __uint_as_float(rec.z);
        float w2 = __uint_as_float(rec.w);
        float wa = (ha == 0) ? w0 : (ha == 1 ? w1 : w2);
        float wb = (hb == 0) ? w0 : (hb == 1 ? w1 : w2);
        if (maskB) wb = 0.f;

        unsigned long long wa2 = f32x2_pack(wa, wa);
        unsigned long long wb2 = f32x2_pack(wb, wb);
        float2 f01 = __half22float2(*reinterpret_cast<__half2*>(&q.x));
        float2 f23 = __half22float2(*reinterpret_cast<__half2*>(&q.y));
        float2 f45 = __half22float2(*reinterpret_cast<__half2*>(&q.z));
        float2 f67 = __half22float2(*reinterpret_cast<__half2*>(&q.w));
        a01 = f32x2_fma(f32x2_pack(f01.x, f01.y), wa2, a01);
        a23 = f32x2_fma(f32x2_pack(f23.x, f23.y), wa2, a23);
        a45 = f32x2_fma(f32x2_pack(f45.x, f45.y), wb2, a45);
        a67 = f32x2_fma(f32x2_pack(f67.x, f67.y), wb2, a67);
    }

    float acc[8];
    f32x2_unpack(a01, acc[0], acc[1]);
    f32x2_unpack(a23, acc[2], acc[3]);
    f32x2_unpack(a45, acc[4], acc[5]);
    f32x2_unpack(a67, acc[6], acc[7]);

    // 6-group stride-5 reduction (hazard-free two-stage)
#pragma unroll
    for (int i = 0; i < 8; i++) {
        float t = acc[i];
        t += __shfl_down_sync(FULL, t, 15);
        float a5  = __shfl_down_sync(FULL, t, 5);
        float a10 = __shfl_down_sync(FULL, t, 10);
        acc[i] = t + a5 + a10;
    }

    if (lane < 5) {
        float4 dn = g_den4[n];
        float inv0 = 1.0f / fmaxf(dn.x, 1e-9f);
        float inv1 = 1.0f / fmaxf(dn.y, 1e-9f);
        float inv2 = 1.0f / fmaxf(dn.z, 1e-9f);
        float va = (ha == 0) ? inv0 : (ha == 1 ? inv1 : inv2);
        float vb = (hb == 0) ? inv0 : (hb == 1 ? inv1 : inv2);

        float* rp = g_rst + n * HID + 8 * lane;
        float4 r0 = *reinterpret_cast<float4*>(rp);
        r0.x += acc[0] * va;
        r0.y += acc[1] * va;
        r0.z += acc[2] * va;
        r0.w += acc[3] * va;
        *reinterpret_cast<float4*>(rp) = r0;
        if (lane < 4) {
            float4 r1 = *reinterpret_cast<float4*>(rp + 4);
            r1.x += acc[4] * vb;
            r1.y += acc[5] * vb;
            r1.z += acc[6] * vb;
            r1.w += acc[7] * vb;
            *reinterpret_cast<float4*>(rp + 4) = r1;
        }
    }
}

// ============================================================================
// Node kernel layers 1,2
// ============================================================================
__global__ __launch_bounds__(128)
void node_prep_mid(const float* __restrict__ fc_w,
                   const float* __restrict__ a_l, const float* __restrict__ a_r,
                   const float* __restrict__ bias, int n_nodes) {
    __shared__ float sW[HID * HID];
    __shared__ float sAl[HID], sAr[HID], sB[HID];

    int tid = threadIdx.x;
    for (int i = tid; i < HID * HID; i += blockDim.x) sW[i] = fc_w[i];
    if (tid < HID) {
        sAl[tid] = a_l[tid];
        sAr[tid] = a_r[tid];
        sB[tid]  = bias[tid];
    }
    __syncthreads();

    int n = blockIdx.x * blockDim.x + tid;
    if (n >= n_nodes) return;

    float x[HID];
#pragma unroll
    for (int k = 0; k < HID; k++) {
        float v = g_rst[n * HID + k];
        x[k] = v > 0.f ? v : expm1f(v);   // ELU
    }

    float f[HID];
#pragma unroll
    for (int j = 0; j < HID; j++) {
        float a = 0.f;
#pragma unroll
        for (int k = 0; k < HID; k++) a += x[k] * sW[k * HID + j];
        f[j] = a;
    }

#pragma unroll
    for (int j = 0; j < HID; j++)
        g_rst[n * HID + j] = x[j] + sB[j];

    float el[NH], er[NH];
#pragma unroll
    for (int h = 0; h < NH; h++) {
        float l = 0.f, r = 0.f;
#pragma unroll
        for (int d = 0; d < HD; d++) {
            l += f[h * HD + d] * sAl[h * HD + d];
            r += f[h * HD + d] * sAr[h * HD + d];
        }
        el[h] = l;
        er[h] = r;
    }
    g_el4[n] = make_float4(el[0], el[1], el[2], 0.f);
    g_er4[n] = make_float4(er[0], er[1], er[2], 0.f);

    unsigned u[20];
#pragma unroll
    for (int i = 0; i < 18; i++) u[i] = pack2(f[2 * i], f[2 * i + 1]);
    u[18] = 0;
    u[19] = 0;
    uint4* dp = reinterpret_cast<uint4*>(g_fe + n * FEH);
#pragma unroll
    for (int i = 0; i < 5; i++)
        dp[i] = make_uint4(u[4 * i], u[4 * i + 1], u[4 * i + 2], u[4 * i + 3]);
}

// ============================================================================
// Output: out = elu(rst) @ out_w + out_b; reset scratch for next call
// ============================================================================
__global__ __launch_bounds__(128)
void out_proj(const float* __restrict__ out_w, const float* __restrict__ out_b,
              float* __restrict__ out, int n_nodes) {
    __shared__ float sW[HID * HID];
    __shared__ float sB[HID];
    int tid = threadIdx.x;
    for (int i = tid; i < HID * HID; i += blockDim.x) sW[i] = out_w[i];
    if (tid < HID) sB[tid] = out_b[tid];
    __syncthreads();

    int n = blockIdx.x * blockDim.x + tid;
    if (n >= n_nodes) return;

    g_deg[n] = 0;
    if (n == 0) g_total = 0;

    float x[HID];
#pragma unroll
    for (int k = 0; k < HID; k++) {
        float v = g_rst[n * HID + k];
        x[k] = v > 0.f ? v : expm1f(v);
    }
#pragma unroll
    for (int j = 0; j < HID; j++) {
        float a = sB[j];
#pragma unroll
        for (int k = 0; k < HID; k++) a += x[k] * sW[k * HID + j];
        out[n * HID + j] = a;
    }
}

// ============================================================================
extern "C" void kernel_launch(void* const* d_in, const int* in_sizes, int n_in,
                              void* d_out, int out_size) {
    const float* node_features = (const float*)d_in[0];
    const int*   src           = (const int*)  d_in[1];
    const int*   dst           = (const int*)  d_in[2];
    const float* lin0_w        = (const float*)d_in[3];
    const float* lin0_b        = (const float*)d_in[4];
    const float* fc_w          = (const float*)d_in[5];
    const float* attn_l        = (const float*)d_in[6];
    const float* attn_r        = (const float*)d_in[7];
    const float* gat_bias      = (const float*)d_in[8];
    const float* out_w         = (const float*)d_in[9];
    const float* out_b         = (const float*)d_in[10];

    int n  = in_sizes[0] / HID;
    int ne = in_sizes[1];

    int nb_np  = (n + 255) / 256;
    int nb_n   = (n + 127) / 128;
    int nb_s   = 148 * 4;
    int nb_g   = (n * 32 + 255) / 256;   // one warp per node

    prep0_hist<<<nb_np + nb_s, 256>>>(node_features, lin0_w, lin0_b,
                                      fc_w, attn_l, attn_r, gat_bias,
                                      dst, n, ne, nb_np);
    scan_fused<<<nb_np, 256>>>(n);
    scatter<<<nb_s, 256>>>(src, dst, ne);

    edge_w<<<nb_g, 256>>>(n);       // launch 3 (profiled)
    gather_agg<<<nb_g, 256>>>(n);

    for (int l = 1; l < 3; l++) {
        node_prep_mid<<<nb_n, 128>>>(fc_w + l * HID * HID,
                                     attn_l + l * HID, attn_r + l * HID,
                                     gat_bias + l * HID, n);
        edge_w<<<nb_g, 256>>>(n);
        gather_agg<<<nb_g, 256>>>(n);
    }
    out_proj<<<nb_n, 128>>>(out_w, out_b, (float*)d_out, n);
}

// round 10
// speedup vs baseline: 1.0738x; 1.0738x over previous
#include <cuda_runtime.h>
#include <cuda_bf16.h>
#include <cuda_fp16.h>

#define NN 100000
#define NE 3200000
#define HID 36
#define NH 3
#define HD 12
#define FEH 48           // fp16 feat row stride in halves: 36 feat + pad = 96B
#define ESRC_CAP (NE + 5 * NN + 64)
#define CAP 156          // per-node smem rec capacity (multiple of 6)
#define CAPP (CAP + 6)   // + prefetch pad
#define FULL 0xffffffffu

// ---- persistent scratch ----
__device__ __align__(128) __half g_fe[(NN + 1) * FEH]; // row NN = zero pad row (never written)
__device__ float4 g_el4[NN + 1];     // el per node (+ pad row = -300)
__device__ float4 g_er4[NN];
__device__ float  g_rst[NN * HID];   // x + bias (+ msg added by gather)
__device__ int   g_deg[NN];          // zero-init; out_proj re-zeroes
__device__ int   g_off[NN];
__device__ int   g_end[NN];          // padded end (multiple of 6)
__device__ int   g_cursor[NN];
__device__ int   g_esrc[ESRC_CAP];
__device__ int   g_total;            // zero-init; out_proj re-zeroes

__device__ __forceinline__ unsigned pack2(float a, float b) {
    __half2 h = __floats2half2_rn(a, b);
    return *reinterpret_cast<unsigned*>(&h);
}
__device__ __forceinline__ unsigned long long f32x2_pack(float lo, float hi) {
    unsigned long long r;
    asm("mov.b64 %0, {%1, %2};" : "=l"(r) : "f"(lo), "f"(hi));
    return r;
}
__device__ __forceinline__ unsigned long long f32x2_fma(unsigned long long a,
                                                        unsigned long long b,
                                                        unsigned long long c) {
    unsigned long long d;
    asm("fma.rn.f32x2 %0, %1, %2, %3;" : "=l"(d) : "l"(a), "l"(b), "l"(c));
    return d;
}
__device__ __forceinline__ void f32x2_unpack(unsigned long long v, float& lo, float& hi) {
    asm("mov.b64 {%0, %1}, %2;" : "=f"(lo), "=f"(hi) : "l"(v));
}

// ============================================================================
// Launch 0: fused node_prep<layer0> (blocks [0,np_blocks)) + hist (rest).
// ============================================================================
__global__ __launch_bounds__(256)
void prep0_hist(const float* __restrict__ in,
                const float* __restrict__ lin0_w, const float* __restrict__ lin0_b,
                const float* __restrict__ fc_w,
                const float* __restrict__ a_l, const float* __restrict__ a_r,
                const float* __restrict__ bias,
                const int* __restrict__ dst,
                int n_nodes, int ne, int np_blocks) {
    if (blockIdx.x >= np_blocks) {
        int bid = blockIdx.x - np_blocks;
        int nb  = gridDim.x - np_blocks;
        int tid = bid * 256 + threadIdx.x;
        int stride = nb * 256;
        int nv = ne >> 2;
        const int4* d4 = reinterpret_cast<const int4*>(dst);
        for (int i = tid; i < nv; i += stride) {
            int4 d = __ldg(&d4[i]);
            atomicAdd(&g_deg[d.x], 1);
            atomicAdd(&g_deg[d.y], 1);
            atomicAdd(&g_deg[d.z], 1);
            atomicAdd(&g_deg[d.w], 1);
        }
        for (int i = (nv << 2) + tid; i < ne; i += stride)
            atomicAdd(&g_deg[dst[i]], 1);
        return;
    }

    __shared__ float sW[HID * HID];
    __shared__ float sW0[HID * HID];
    __shared__ float sAl[HID], sAr[HID], sB[HID], sB0[HID];

    int tid = threadIdx.x;
    for (int i = tid; i < HID * HID; i += 256) {
        sW[i]  = fc_w[i];
        sW0[i] = lin0_w[i];
    }
    if (tid < HID) {
        sAl[tid] = a_l[tid];
        sAr[tid] = a_r[tid];
        sB[tid]  = bias[tid];
        sB0[tid] = lin0_b[tid];
    }
    __syncthreads();

    int n = blockIdx.x * 256 + tid;
    if (n >= n_nodes) return;

    float nf[HID], x[HID];
#pragma unroll
    for (int k = 0; k < HID; k++) nf[k] = in[n * HID + k];
#pragma unroll
    for (int j = 0; j < HID; j++) {
        float a = sB0[j];
#pragma unroll
        for (int k = 0; k < HID; k++) a += nf[k] * sW0[k * HID + j];
        x[j] = a;
    }

    float f[HID];
#pragma unroll
    for (int j = 0; j < HID; j++) {
        float a = 0.f;
#pragma unroll
        for (int k = 0; k < HID; k++) a += x[k] * sW[k * HID + j];
        f[j] = a;
    }

#pragma unroll
    for (int j = 0; j < HID; j++)
        g_rst[n * HID + j] = x[j] + sB[j];

    float el[NH], er[NH];
#pragma unroll
    for (int h = 0; h < NH; h++) {
        float l = 0.f, r = 0.f;
#pragma unroll
        for (int d = 0; d < HD; d++) {
            l += f[h * HD + d] * sAl[h * HD + d];
            r += f[h * HD + d] * sAr[h * HD + d];
        }
        el[h] = l;
        er[h] = r;
    }
    g_el4[n] = make_float4(el[0], el[1], el[2], 0.f);
    g_er4[n] = make_float4(er[0], er[1], er[2], 0.f);

    unsigned u[20];
#pragma unroll
    for (int i = 0; i < 18; i++) u[i] = pack2(f[2 * i], f[2 * i + 1]);
    u[18] = 0;
    u[19] = 0;
    uint4* dp = reinterpret_cast<uint4*>(g_fe + n * FEH);
#pragma unroll
    for (int i = 0; i < 5; i++)
        dp[i] = make_uint4(u[4 * i], u[4 * i + 1], u[4 * i + 2], u[4 * i + 3]);
}

// ============================================================================
// Launch 1: single-pass scan over PADDED degrees (ceil to multiple of 6);
// fills pad slots with src = NN (zero node). Sets pad node's el row.
// ============================================================================
__global__ __launch_bounds__(256)
void scan_fused(int n) {
    __shared__ int sh[256];
    __shared__ int sbase;
    int t = threadIdx.x;
    int i = blockIdx.x * 256 + t;
    int deg = (i < n) ? g_deg[i] : 0;
    int pd = ((deg + 5) / 6) * 6;
    sh[t] = pd;
    __syncthreads();
    for (int d = 1; d < 256; d <<= 1) {
        int x = (t >= d) ? sh[t - d] : 0;
        __syncthreads();
        sh[t] += x;
        __syncthreads();
    }
    int incl = sh[t];
    if (t == 255) sbase = atomicAdd(&g_total, incl);
    __syncthreads();
    if (i < n) {
        int off = sbase + incl - pd;
        g_off[i] = off;
        g_end[i] = off + pd;
        g_cursor[i] = off;
        for (int j = off + deg; j < off + pd; j++)
            g_esrc[j] = NN;                 // pad slots -> zero node
    }
    if (blockIdx.x == 0 && t == 0)
        g_el4[NN] = make_float4(-300.f, -300.f, -300.f, 0.f); // w -> ~0
}

// ============================================================================
// Launch 2: scatter src into CSR slots
// ============================================================================
__global__ __launch_bounds__(256)
void scatter(const int* __restrict__ src, const int* __restrict__ dst, int ne) {
    int tid = blockIdx.x * blockDim.x + threadIdx.x;
    int stride = gridDim.x * blockDim.x;
    int nv = ne >> 2;
    const int4* s4 = reinterpret_cast<const int4*>(src);
    const int4* d4 = reinterpret_cast<const int4*>(dst);
    for (int i = tid; i < nv; i += stride) {
        int4 s = __ldg(&s4[i]);
        int4 d = __ldg(&d4[i]);
        int p0 = atomicAdd(&g_cursor[d.x], 1);
        int p1 = atomicAdd(&g_cursor[d.y], 1);
        int p2 = atomicAdd(&g_cursor[d.z], 1);
        int p3 = atomicAdd(&g_cursor[d.w], 1);
        g_esrc[p0] = s.x;
        g_esrc[p1] = s.y;
        g_esrc[p2] = s.z;
        g_esrc[p3] = s.w;
    }
    for (int i = (nv << 2) + tid; i < ne; i += stride) {
        int pos = atomicAdd(&g_cursor[dst[i]], 1);
        g_esrc[pos] = src[i];
    }
}

// ============================================================================
// Fused per-layer edge kernel: one warp per dst node.
// Phase 1 (lane-per-edge): w = exp(leaky(el[src]+er[n])) per head; den reduced
// in registers; {src,w0,w1,w2} staged in per-warp SMEM (CAP edges).
// Phase 2 (6 edges x 5 lanes): rec from LDS (prefetched 1 ahead), feat LDG,
// packed f32x2 FMA. Overflow (deg > CAP, ~never) recomputes w inline.
// ============================================================================
__global__ __launch_bounds__(256)
void layer_edge(int n_nodes) {
    __shared__ float4 swrec[8][CAPP];

    int warp = (blockIdx.x * blockDim.x + threadIdx.x) >> 5;
    if (warp >= n_nodes) return;
    int wib  = threadIdx.x >> 5;
    int lane = threadIdx.x & 31;
    int n = warp;

    int beg = g_off[n];
    int pd  = g_end[n] - beg;        // padded degree (multiple of 6)
    float4 er = g_er4[n];

    // ---- phase 1: weights + denominator ----
    float d0 = 0.f, d1 = 0.f, d2 = 0.f;
    for (int j = lane; j < pd; j += 32) {
        int s = __ldg(&g_esrc[beg + j]);
        float4 el = __ldg(&g_el4[s]);
        float v0 = el.x + er.x;
        float v1 = el.y + er.y;
        float v2 = el.z + er.z;
        v0 = v0 >= 0.f ? v0 : 0.2f * v0;
        v1 = v1 >= 0.f ? v1 : 0.2f * v1;
        v2 = v2 >= 0.f ? v2 : 0.2f * v2;
        float w0 = __expf(v0);
        float w1 = __expf(v1);
        float w2 = __expf(v2);
        d0 += w0; d1 += w1; d2 += w2;
        if (j < CAP) swrec[wib][j] = make_float4(__int_as_float(s), w0, w1, w2);
    }
    // prefetch pad recs
    int mend = min(pd, CAP);
    if (lane < 6)
        swrec[wib][mend + lane] = make_float4(__int_as_float((int)NN), 0.f, 0.f, 0.f);

#pragma unroll
    for (int o = 16; o > 0; o >>= 1) {
        d0 += __shfl_xor_sync(FULL, d0, o);
        d1 += __shfl_xor_sync(FULL, d1, o);
        d2 += __shfl_xor_sync(FULL, d2, o);
    }
    __syncwarp();

    // ---- phase 2: gather-aggregate ----
    int e = lane / 5;          // 0..5 valid; 6 for lanes 30,31
    int c = lane - e * 5;      // 0..4
    bool laneOk = lane < 30;
    int esafe = laneOk ? e : 0;

    int ha = (c < 2) ? 0 : (c == 2 ? 1 : 2);
    int hb = (c == 0) ? 0 : (c < 3 ? 1 : 2);
    bool maskB = (c == 4);

    unsigned long long a01 = 0, a23 = 0, a45 = 0, a67 = 0;

    float4 rec = swrec[wib][esafe];
    for (int i = 0; i < mend; i += 6) {
        float4 cur = rec;
        rec = swrec[wib][i + 6 + esafe];          // pads guarantee validity

        int s = laneOk ? __float_as_int(cur.x) : NN;
        uint4 q = __ldg(reinterpret_cast<const uint4*>(g_fe + s * FEH) + c);

        float wa = (ha == 0) ? cur.y : (ha == 1 ? cur.z : cur.w);
        float wb = (hb == 0) ? cur.y : (hb == 1 ? cur.z : cur.w);
        if (maskB) wb = 0.f;

        unsigned long long wa2 = f32x2_pack(wa, wa);
        unsigned long long wb2 = f32x2_pack(wb, wb);
        float2 f01 = __half22float2(*reinterpret_cast<__half2*>(&q.x));
        float2 f23 = __half22float2(*reinterpret_cast<__half2*>(&q.y));
        float2 f45 = __half22float2(*reinterpret_cast<__half2*>(&q.z));
        float2 f67 = __half22float2(*reinterpret_cast<__half2*>(&q.w));
        a01 = f32x2_fma(f32x2_pack(f01.x, f01.y), wa2, a01);
        a23 = f32x2_fma(f32x2_pack(f23.x, f23.y), wa2, a23);
        a45 = f32x2_fma(f32x2_pack(f45.x, f45.y), wb2, a45);
        a67 = f32x2_fma(f32x2_pack(f67.x, f67.y), wb2, a67);
    }

    // overflow path (deg > CAP): recompute w inline; ~never taken
    for (int i = CAP; i < pd; i += 6) {
        int s = laneOk ? __ldg(&g_esrc[beg + i + esafe]) : NN;
        float4 el = __ldg(&g_el4[s]);
        float v0 = el.x + er.x;
        float v1 = el.y + er.y;
        float v2 = el.z + er.z;
        v0 = v0 >= 0.f ? v0 : 0.2f * v0;
        v1 = v1 >= 0.f ? v1 : 0.2f * v1;
        v2 = v2 >= 0.f ? v2 : 0.2f * v2;
        float w0 = __expf(v0);
        float w1 = __expf(v1);
        float w2 = __expf(v2);

        uint4 q = __ldg(reinterpret_cast<const uint4*>(g_fe + s * FEH) + c);
        float wa = (ha == 0) ? w0 : (ha == 1 ? w1 : w2);
        float wb = (hb == 0) ? w0 : (hb == 1 ? w1 : w2);
        if (maskB) wb = 0.f;

        unsigned long long wa2 = f32x2_pack(wa, wa);
        unsigned long long wb2 = f32x2_pack(wb, wb);
        float2 f01 = __half22float2(*reinterpret_cast<__half2*>(&q.x));
        float2 f23 = __half22float2(*reinterpret_cast<__half2*>(&q.y));
        float2 f45 = __half22float2(*reinterpret_cast<__half2*>(&q.z));
        float2 f67 = __half22float2(*reinterpret_cast<__half2*>(&q.w));
        a01 = f32x2_fma(f32x2_pack(f01.x, f01.y), wa2, a01);
        a23 = f32x2_fma(f32x2_pack(f23.x, f23.y), wa2, a23);
        a45 = f32x2_fma(f32x2_pack(f45.x, f45.y), wb2, a45);
        a67 = f32x2_fma(f32x2_pack(f67.x, f67.y), wb2, a67);
    }

    float acc[8];
    f32x2_unpack(a01, acc[0], acc[1]);
    f32x2_unpack(a23, acc[2], acc[3]);
    f32x2_unpack(a45, acc[4], acc[5]);
    f32x2_unpack(a67, acc[6], acc[7]);

    // 6-group stride-5 reduction (hazard-free two-stage)
#pragma unroll
    for (int i = 0; i < 8; i++) {
        float t = acc[i];
        t += __shfl_down_sync(FULL, t, 15);
        float a5  = __shfl_down_sync(FULL, t, 5);
        float a10 = __shfl_down_sync(FULL, t, 10);
        acc[i] = t + a5 + a10;
    }

    if (lane < 5) {
        float inv0 = 1.0f / fmaxf(d0, 1e-9f);
        float inv1 = 1.0f / fmaxf(d1, 1e-9f);
        float inv2 = 1.0f / fmaxf(d2, 1e-9f);
        float va = (ha == 0) ? inv0 : (ha == 1 ? inv1 : inv2);
        float vb = (hb == 0) ? inv0 : (hb == 1 ? inv1 : inv2);

        float* rp = g_rst + n * HID + 8 * lane;
        float4 r0 = *reinterpret_cast<float4*>(rp);
        r0.x += acc[0] * va;
        r0.y += acc[1] * va;
        r0.z += acc[2] * va;
        r0.w += acc[3] * va;
        *reinterpret_cast<float4*>(rp) = r0;
        if (lane < 4) {
            float4 r1 = *reinterpret_cast<float4*>(rp + 4);
            r1.x += acc[4] * vb;
            r1.y += acc[5] * vb;
            r1.z += acc[6] * vb;
            r1.w += acc[7] * vb;
            *reinterpret_cast<float4*>(rp + 4) = r1;
        }
    }
}

// ============================================================================
// Node kernel layers 1,2
// ============================================================================
__global__ __launch_bounds__(128)
void node_prep_mid(const float* __restrict__ fc_w,
                   const float* __restrict__ a_l, const float* __restrict__ a_r,
                   const float* __restrict__ bias, int n_nodes) {
    __shared__ float sW[HID * HID];
    __shared__ float sAl[HID], sAr[HID], sB[HID];

    int tid = threadIdx.x;
    for (int i = tid; i < HID * HID; i += blockDim.x) sW[i] = fc_w[i];
    if (tid < HID) {
        sAl[tid] = a_l[tid];
        sAr[tid] = a_r[tid];
        sB[tid]  = bias[tid];
    }
    __syncthreads();

    int n = blockIdx.x * blockDim.x + tid;
    if (n >= n_nodes) return;

    float x[HID];
#pragma unroll
    for (int k = 0; k < HID; k++) {
        float v = g_rst[n * HID + k];
        x[k] = v > 0.f ? v : expm1f(v);   // ELU
    }

    float f[HID];
#pragma unroll
    for (int j = 0; j < HID; j++) {
        float a = 0.f;
#pragma unroll
        for (int k = 0; k < HID; k++) a += x[k] * sW[k * HID + j];
        f[j] = a;
    }

#pragma unroll
    for (int j = 0; j < HID; j++)
        g_rst[n * HID + j] = x[j] + sB[j];

    float el[NH], er[NH];
#pragma unroll
    for (int h = 0; h < NH; h++) {
        float l = 0.f, r = 0.f;
#pragma unroll
        for (int d = 0; d < HD; d++) {
            l += f[h * HD + d] * sAl[h * HD + d];
            r += f[h * HD + d] * sAr[h * HD + d];
        }
        el[h] = l;
        er[h] = r;
    }
    g_el4[n] = make_float4(el[0], el[1], el[2], 0.f);
    g_er4[n] = make_float4(er[0], er[1], er[2], 0.f);

    unsigned u[20];
#pragma unroll
    for (int i = 0; i < 18; i++) u[i] = pack2(f[2 * i], f[2 * i + 1]);
    u[18] = 0;
    u[19] = 0;
    uint4* dp = reinterpret_cast<uint4*>(g_fe + n * FEH);
#pragma unroll
    for (int i = 0; i < 5; i++)
        dp[i] = make_uint4(u[4 * i], u[4 * i + 1], u[4 * i + 2], u[4 * i + 3]);
}

// ============================================================================
// Output: out = elu(rst) @ out_w + out_b; reset scratch for next call
// ============================================================================
__global__ __launch_bounds__(128)
void out_proj(const float* __restrict__ out_w, const float* __restrict__ out_b,
              float* __restrict__ out, int n_nodes) {
    __shared__ float sW[HID * HID];
    __shared__ float sB[HID];
    int tid = threadIdx.x;
    for (int i = tid; i < HID * HID; i += blockDim.x) sW[i] = out_w[i];
    if (tid < HID) sB[tid] = out_b[tid];
    __syncthreads();

    int n = blockIdx.x * blockDim.x + tid;
    if (n >= n_nodes) return;

    g_deg[n] = 0;
    if (n == 0) g_total = 0;

    float x[HID];
#pragma unroll
    for (int k = 0; k < HID; k++) {
        float v = g_rst[n * HID + k];
        x[k] = v > 0.f ? v : expm1f(v);
    }
#pragma unroll
    for (int j = 0; j < HID; j++) {
        float a = sB[j];
#pragma unroll
        for (int k = 0; k < HID; k++) a += x[k] * sW[k * HID + j];
        out[n * HID + j] = a;
    }
}

// ============================================================================
extern "C" void kernel_launch(void* const* d_in, const int* in_sizes, int n_in,
                              void* d_out, int out_size) {
    const float* node_features = (const float*)d_in[0];
    const int*   src           = (const int*)  d_in[1];
    const int*   dst           = (const int*)  d_in[2];
    const float* lin0_w        = (const float*)d_in[3];
    const float* lin0_b        = (const float*)d_in[4];
    const float* fc_w          = (const float*)d_in[5];
    const float* attn_l        = (const float*)d_in[6];
    const float* attn_r        = (const float*)d_in[7];
    const float* gat_bias      = (const float*)d_in[8];
    const float* out_w         = (const float*)d_in[9];
    const float* out_b         = (const float*)d_in[10];

    int n  = in_sizes[0] / HID;
    int ne = in_sizes[1];

    int nb_np  = (n + 255) / 256;
    int nb_n   = (n + 127) / 128;
    int nb_s   = 148 * 4;
    int nb_g   = (n * 32 + 255) / 256;   // one warp per node

    prep0_hist<<<nb_np + nb_s, 256>>>(node_features, lin0_w, lin0_b,
                                      fc_w, attn_l, attn_r, gat_bias,
                                      dst, n, ne, nb_np);
    scan_fused<<<nb_np, 256>>>(n);
    scatter<<<nb_s, 256>>>(src, dst, ne);

    layer_edge<<<nb_g, 256>>>(n);        // launch 3 (profiled)

    for (int l = 1; l < 3; l++) {
        node_prep_mid<<<nb_n, 128>>>(fc_w + l * HID * HID,
                                     attn_l + l * HID, attn_r + l * HID,
                                     gat_bias + l * HID, n);
        layer_edge<<<nb_g, 256>>>(n);
    }
    out_proj<<<nb_n, 128>>>(out_w, out_b, (float*)d_out, n);
}

// round 11
// speedup vs baseline: 1.1371x; 1.0589x over previous
#include <cuda_runtime.h>
#include <cuda_bf16.h>
#include <cuda_fp16.h>

#define NN 100000
#define NE 3200000
#define HID 36
#define NH 3
#define HD 12
#define FEH 48           // fp16 feat row stride in halves: 36 feat + pad = 96B
#define ESRC_CAP (NE + 5 * NN + 64)
#define CAP 90           // per-node smem rec capacity (multiple of 6)
#define CAPP (CAP + 6)   // + prefetch pad
#define FULL 0xffffffffu

// ---- persistent scratch ----
__device__ __align__(128) __half g_fe[(NN + 1) * FEH]; // row NN = zero pad row (never written)
__device__ float4 g_el4[NN + 1];     // el per node (+ pad row = -300)
__device__ float4 g_er4[NN];
__device__ float  g_rst[NN * HID];   // x + bias (+ msg added by gather)
__device__ int   g_deg[NN];          // zero-init; out_proj re-zeroes
__device__ int   g_off[NN];
__device__ int   g_end[NN];          // padded end (multiple of 6)
__device__ int   g_cursor[NN];
__device__ int   g_esrc[ESRC_CAP];
__device__ int   g_total;            // zero-init; out_proj re-zeroes

__device__ __forceinline__ unsigned pack2(float a, float b) {
    __half2 h = __floats2half2_rn(a, b);
    return *reinterpret_cast<unsigned*>(&h);
}
__device__ __forceinline__ unsigned long long f32x2_pack(float lo, float hi) {
    unsigned long long r;
    asm("mov.b64 %0, {%1, %2};" : "=l"(r) : "f"(lo), "f"(hi));
    return r;
}
__device__ __forceinline__ unsigned long long f32x2_fma(unsigned long long a,
                                                        unsigned long long b,
                                                        unsigned long long c) {
    unsigned long long d;
    asm("fma.rn.f32x2 %0, %1, %2, %3;" : "=l"(d) : "l"(a), "l"(b), "l"(c));
    return d;
}
__device__ __forceinline__ void f32x2_unpack(unsigned long long v, float& lo, float& hi) {
    asm("mov.b64 {%0, %1}, %2;" : "=f"(lo), "=f"(hi) : "l"(v));
}

// ============================================================================
// Launch 0: fused node_prep<layer0> (blocks [0,np_blocks)) + hist (rest).
// ============================================================================
__global__ __launch_bounds__(256)
void prep0_hist(const float* __restrict__ in,
                const float* __restrict__ lin0_w, const float* __restrict__ lin0_b,
                const float* __restrict__ fc_w,
                const float* __restrict__ a_l, const float* __restrict__ a_r,
                const float* __restrict__ bias,
                const int* __restrict__ dst,
                int n_nodes, int ne, int np_blocks) {
    if (blockIdx.x >= np_blocks) {
        int bid = blockIdx.x - np_blocks;
        int nb  = gridDim.x - np_blocks;
        int tid = bid * 256 + threadIdx.x;
        int stride = nb * 256;
        int nv = ne >> 2;
        const int4* d4 = reinterpret_cast<const int4*>(dst);
        for (int i = tid; i < nv; i += stride) {
            int4 d = __ldg(&d4[i]);
            atomicAdd(&g_deg[d.x], 1);
            atomicAdd(&g_deg[d.y], 1);
            atomicAdd(&g_deg[d.z], 1);
            atomicAdd(&g_deg[d.w], 1);
        }
        for (int i = (nv << 2) + tid; i < ne; i += stride)
            atomicAdd(&g_deg[dst[i]], 1);
        return;
    }

    __shared__ float sW[HID * HID];
    __shared__ float sW0[HID * HID];
    __shared__ float sAl[HID], sAr[HID], sB[HID], sB0[HID];

    int tid = threadIdx.x;
    for (int i = tid; i < HID * HID; i += 256) {
        sW[i]  = fc_w[i];
        sW0[i] = lin0_w[i];
    }
    if (tid < HID) {
        sAl[tid] = a_l[tid];
        sAr[tid] = a_r[tid];
        sB[tid]  = bias[tid];
        sB0[tid] = lin0_b[tid];
    }
    __syncthreads();

    int n = blockIdx.x * 256 + tid;
    if (n >= n_nodes) return;

    float nf[HID], x[HID];
#pragma unroll
    for (int k = 0; k < HID; k++) nf[k] = in[n * HID + k];
#pragma unroll
    for (int j = 0; j < HID; j++) {
        float a = sB0[j];
#pragma unroll
        for (int k = 0; k < HID; k++) a += nf[k] * sW0[k * HID + j];
        x[j] = a;
    }

    float f[HID];
#pragma unroll
    for (int j = 0; j < HID; j++) {
        float a = 0.f;
#pragma unroll
        for (int k = 0; k < HID; k++) a += x[k] * sW[k * HID + j];
        f[j] = a;
    }

#pragma unroll
    for (int j = 0; j < HID; j++)
        g_rst[n * HID + j] = x[j] + sB[j];

    float el[NH], er[NH];
#pragma unroll
    for (int h = 0; h < NH; h++) {
        float l = 0.f, r = 0.f;
#pragma unroll
        for (int d = 0; d < HD; d++) {
            l += f[h * HD + d] * sAl[h * HD + d];
            r += f[h * HD + d] * sAr[h * HD + d];
        }
        el[h] = l;
        er[h] = r;
    }
    g_el4[n] = make_float4(el[0], el[1], el[2], 0.f);
    g_er4[n] = make_float4(er[0], er[1], er[2], 0.f);

    unsigned u[20];
#pragma unroll
    for (int i = 0; i < 18; i++) u[i] = pack2(f[2 * i], f[2 * i + 1]);
    u[18] = 0;
    u[19] = 0;
    uint4* dp = reinterpret_cast<uint4*>(g_fe + n * FEH);
#pragma unroll
    for (int i = 0; i < 5; i++)
        dp[i] = make_uint4(u[4 * i], u[4 * i + 1], u[4 * i + 2], u[4 * i + 3]);
}

// ============================================================================
// Launch 1: single-pass scan over PADDED degrees (ceil to multiple of 6);
// fills pad slots with src = NN (zero node). Sets pad node's el row.
// ============================================================================
__global__ __launch_bounds__(256)
void scan_fused(int n) {
    __shared__ int sh[256];
    __shared__ int sbase;
    int t = threadIdx.x;
    int i = blockIdx.x * 256 + t;
    int deg = (i < n) ? g_deg[i] : 0;
    int pd = ((deg + 5) / 6) * 6;
    sh[t] = pd;
    __syncthreads();
    for (int d = 1; d < 256; d <<= 1) {
        int x = (t >= d) ? sh[t - d] : 0;
        __syncthreads();
        sh[t] += x;
        __syncthreads();
    }
    int incl = sh[t];
    if (t == 255) sbase = atomicAdd(&g_total, incl);
    __syncthreads();
    if (i < n) {
        int off = sbase + incl - pd;
        g_off[i] = off;
        g_end[i] = off + pd;
        g_cursor[i] = off;
        for (int j = off + deg; j < off + pd; j++)
            g_esrc[j] = NN;                 // pad slots -> zero node
    }
    if (blockIdx.x == 0 && t == 0)
        g_el4[NN] = make_float4(-300.f, -300.f, -300.f, 0.f); // w -> ~0
}

// ============================================================================
// Launch 2: scatter src into CSR slots
// ============================================================================
__global__ __launch_bounds__(256)
void scatter(const int* __restrict__ src, const int* __restrict__ dst, int ne) {
    int tid = blockIdx.x * blockDim.x + threadIdx.x;
    int stride = gridDim.x * blockDim.x;
    int nv = ne >> 2;
    const int4* s4 = reinterpret_cast<const int4*>(src);
    const int4* d4 = reinterpret_cast<const int4*>(dst);
    for (int i = tid; i < nv; i += stride) {
        int4 s = __ldg(&s4[i]);
        int4 d = __ldg(&d4[i]);
        int p0 = atomicAdd(&g_cursor[d.x], 1);
        int p1 = atomicAdd(&g_cursor[d.y], 1);
        int p2 = atomicAdd(&g_cursor[d.z], 1);
        int p3 = atomicAdd(&g_cursor[d.w], 1);
        g_esrc[p0] = s.x;
        g_esrc[p1] = s.y;
        g_esrc[p2] = s.z;
        g_esrc[p3] = s.w;
    }
    for (int i = (nv << 2) + tid; i < ne; i += stride) {
        int pos = atomicAdd(&g_cursor[dst[i]], 1);
        g_esrc[pos] = src[i];
    }
}

// ============================================================================
// Fused per-layer edge kernel: one warp per dst node.
// Phase 1 (lane-per-edge): w = exp(leaky(el[src]+er[n])) per head; den reduced
// in registers; {src,w0,w1,w2} staged in per-warp SMEM (CAP edges).
// Phase 2 (6 edges x 5 lanes): rec from LDS, feat LDG software-pipelined
// one iteration ahead (pads make the prefetch unconditionally safe).
// __launch_bounds__(256, 6): regs<=42 -> 6 blocks/SM -> 75% occupancy.
// ============================================================================
__global__ __launch_bounds__(256, 6)
void layer_edge(int n_nodes) {
    __shared__ float4 swrec[8][CAPP];

    int warp = (blockIdx.x * blockDim.x + threadIdx.x) >> 5;
    if (warp >= n_nodes) return;
    int wib  = threadIdx.x >> 5;
    int lane = threadIdx.x & 31;
    int n = warp;

    int beg = g_off[n];
    int pd  = g_end[n] - beg;        // padded degree (multiple of 6)
    float4 er = g_er4[n];

    // ---- phase 1: weights + denominator ----
    float d0 = 0.f, d1 = 0.f, d2 = 0.f;
    for (int j = lane; j < pd; j += 32) {
        int s = __ldg(&g_esrc[beg + j]);
        float4 el = __ldg(&g_el4[s]);
        float v0 = el.x + er.x;
        float v1 = el.y + er.y;
        float v2 = el.z + er.z;
        v0 = v0 >= 0.f ? v0 : 0.2f * v0;
        v1 = v1 >= 0.f ? v1 : 0.2f * v1;
        v2 = v2 >= 0.f ? v2 : 0.2f * v2;
        float w0 = __expf(v0);
        float w1 = __expf(v1);
        float w2 = __expf(v2);
        d0 += w0; d1 += w1; d2 += w2;
        if (j < CAP) swrec[wib][j] = make_float4(__int_as_float(s), w0, w1, w2);
    }
    // pad recs for the prefetch window
    int mend = min(pd, CAP);
    if (lane < 6)
        swrec[wib][mend + lane] = make_float4(__int_as_float((int)NN), 0.f, 0.f, 0.f);

#pragma unroll
    for (int o = 16; o > 0; o >>= 1) {
        d0 += __shfl_xor_sync(FULL, d0, o);
        d1 += __shfl_xor_sync(FULL, d1, o);
        d2 += __shfl_xor_sync(FULL, d2, o);
    }
    __syncwarp();

    // ---- phase 2: gather-aggregate, feat LDG pipelined 1 ahead ----
    int e = lane / 5;          // 0..5 valid; 6 for lanes 30,31
    int c = lane - e * 5;      // 0..4
    bool laneOk = lane < 30;
    int esafe = laneOk ? e : 0;

    int ha = (c < 2) ? 0 : (c == 2 ? 1 : 2);
    int hb = (c == 0) ? 0 : (c < 3 ? 1 : 2);
    bool maskB = (c == 4);

    unsigned long long a01 = 0, a23 = 0, a45 = 0, a67 = 0;

    float4 rec = swrec[wib][esafe];
    int scur = laneOk ? __float_as_int(rec.x) : NN;
    uint4 q = __ldg(reinterpret_cast<const uint4*>(g_fe + scur * FEH) + c);

    for (int i = 0; i < mend; i += 6) {
        // prefetch next iteration (pad recs -> always valid; row NN is zero)
        float4 nrec = swrec[wib][i + 6 + esafe];
        int snext = laneOk ? __float_as_int(nrec.x) : NN;
        uint4 nq = __ldg(reinterpret_cast<const uint4*>(g_fe + snext * FEH) + c);

        float wa = (ha == 0) ? rec.y : (ha == 1 ? rec.z : rec.w);
        float wb = (hb == 0) ? rec.y : (hb == 1 ? rec.z : rec.w);
        if (maskB) wb = 0.f;

        unsigned long long wa2 = f32x2_pack(wa, wa);
        unsigned long long wb2 = f32x2_pack(wb, wb);
        float2 f01 = __half22float2(*reinterpret_cast<__half2*>(&q.x));
        float2 f23 = __half22float2(*reinterpret_cast<__half2*>(&q.y));
        float2 f45 = __half22float2(*reinterpret_cast<__half2*>(&q.z));
        float2 f67 = __half22float2(*reinterpret_cast<__half2*>(&q.w));
        a01 = f32x2_fma(f32x2_pack(f01.x, f01.y), wa2, a01);
        a23 = f32x2_fma(f32x2_pack(f23.x, f23.y), wa2, a23);
        a45 = f32x2_fma(f32x2_pack(f45.x, f45.y), wb2, a45);
        a67 = f32x2_fma(f32x2_pack(f67.x, f67.y), wb2, a67);

        rec = nrec;
        q = nq;
    }

    // overflow path (deg > CAP; ~never for Poisson(32) degrees): exact recompute
    for (int i = CAP; i < pd; i += 6) {
        int s = laneOk ? __ldg(&g_esrc[beg + i + esafe]) : NN;
        float4 el = __ldg(&g_el4[s]);
        float v0 = el.x + er.x;
        float v1 = el.y + er.y;
        float v2 = el.z + er.z;
        v0 = v0 >= 0.f ? v0 : 0.2f * v0;
        v1 = v1 >= 0.f ? v1 : 0.2f * v1;
        v2 = v2 >= 0.f ? v2 : 0.2f * v2;
        float w0 = __expf(v0);
        float w1 = __expf(v1);
        float w2 = __expf(v2);

        uint4 qq = __ldg(reinterpret_cast<const uint4*>(g_fe + s * FEH) + c);
        float wa = (ha == 0) ? w0 : (ha == 1 ? w1 : w2);
        float wb = (hb == 0) ? w0 : (hb == 1 ? w1 : w2);
        if (maskB) wb = 0.f;

        unsigned long long wa2 = f32x2_pack(wa, wa);
        unsigned long long wb2 = f32x2_pack(wb, wb);
        float2 f01 = __half22float2(*reinterpret_cast<__half2*>(&qq.x));
        float2 f23 = __half22float2(*reinterpret_cast<__half2*>(&qq.y));
        float2 f45 = __half22float2(*reinterpret_cast<__half2*>(&qq.z));
        float2 f67 = __half22float2(*reinterpret_cast<__half2*>(&qq.w));
        a01 = f32x2_fma(f32x2_pack(f01.x, f01.y), wa2, a01);
        a23 = f32x2_fma(f32x2_pack(f23.x, f23.y), wa2, a23);
        a45 = f32x2_fma(f32x2_pack(f45.x, f45.y), wb2, a45);
        a67 = f32x2_fma(f32x2_pack(f67.x, f67.y), wb2, a67);
    }

    float acc[8];
    f32x2_unpack(a01, acc[0], acc[1]);
    f32x2_unpack(a23, acc[2], acc[3]);
    f32x2_unpack(a45, acc[4], acc[5]);
    f32x2_unpack(a67, acc[6], acc[7]);

    // 6-group stride-5 reduction (hazard-free two-stage)
#pragma unroll
    for (int i = 0; i < 8; i++) {
        float t = acc[i];
        t += __shfl_down_sync(FULL, t, 15);
        float a5  = __shfl_down_sync(FULL, t, 5);
        float a10 = __shfl_down_sync(FULL, t, 10);
        acc[i] = t + a5 + a10;
    }

    if (lane < 5) {
        float inv0 = 1.0f / fmaxf(d0, 1e-9f);
        float inv1 = 1.0f / fmaxf(d1, 1e-9f);
        float inv2 = 1.0f / fmaxf(d2, 1e-9f);
        float va = (ha == 0) ? inv0 : (ha == 1 ? inv1 : inv2);
        float vb = (hb == 0) ? inv0 : (hb == 1 ? inv1 : inv2);

        float* rp = g_rst + n * HID + 8 * lane;
        float4 r0 = *reinterpret_cast<float4*>(rp);
        r0.x += acc[0] * va;
        r0.y += acc[1] * va;
        r0.z += acc[2] * va;
        r0.w += acc[3] * va;
        *reinterpret_cast<float4*>(rp) = r0;
        if (lane < 4) {
            float4 r1 = *reinterpret_cast<float4*>(rp + 4);
            r1.x += acc[4] * vb;
            r1.y += acc[5] * vb;
            r1.z += acc[6] * vb;
            r1.w += acc[7] * vb;
            *reinterpret_cast<float4*>(rp + 4) = r1;
        }
    }
}

// ============================================================================
// Node kernel layers 1,2
// ============================================================================
__global__ __launch_bounds__(128)
void node_prep_mid(const float* __restrict__ fc_w,
                   const float* __restrict__ a_l, const float* __restrict__ a_r,
                   const float* __restrict__ bias, int n_nodes) {
    __shared__ float sW[HID * HID];
    __shared__ float sAl[HID], sAr[HID], sB[HID];

    int tid = threadIdx.x;
    for (int i = tid; i < HID * HID; i += blockDim.x) sW[i] = fc_w[i];
    if (tid < HID) {
        sAl[tid] = a_l[tid];
        sAr[tid] = a_r[tid];
        sB[tid]  = bias[tid];
    }
    __syncthreads();

    int n = blockIdx.x * blockDim.x + tid;
    if (n >= n_nodes) return;

    float x[HID];
#pragma unroll
    for (int k = 0; k < HID; k++) {
        float v = g_rst[n * HID + k];
        x[k] = v > 0.f ? v : expm1f(v);   // ELU
    }

    float f[HID];
#pragma unroll
    for (int j = 0; j < HID; j++) {
        float a = 0.f;
#pragma unroll
        for (int k = 0; k < HID; k++) a += x[k] * sW[k * HID + j];
        f[j] = a;
    }

#pragma unroll
    for (int j = 0; j < HID; j++)
        g_rst[n * HID + j] = x[j] + sB[j];

    float el[NH], er[NH];
#pragma unroll
    for (int h = 0; h < NH; h++) {
        float l = 0.f, r = 0.f;
#pragma unroll
        for (int d = 0; d < HD; d++) {
            l += f[h * HD + d] * sAl[h * HD + d];
            r += f[h * HD + d] * sAr[h * HD + d];
        }
        el[h] = l;
        er[h] = r;
    }
    g_el4[n] = make_float4(el[0], el[1], el[2], 0.f);
    g_er4[n] = make_float4(er[0], er[1], er[2], 0.f);

    unsigned u[20];
#pragma unroll
    for (int i = 0; i < 18; i++) u[i] = pack2(f[2 * i], f[2 * i + 1]);
    u[18] = 0;
    u[19] = 0;
    uint4* dp = reinterpret_cast<uint4*>(g_fe + n * FEH);
#pragma unroll
    for (int i = 0; i < 5; i++)
        dp[i] = make_uint4(u[4 * i], u[4 * i + 1], u[4 * i + 2], u[4 * i + 3]);
}

// ============================================================================
// Output: out = elu(rst) @ out_w + out_b; reset scratch for next call
// ============================================================================
__global__ __launch_bounds__(128)
void out_proj(const float* __restrict__ out_w, const float* __restrict__ out_b,
              float* __restrict__ out, int n_nodes) {
    __shared__ float sW[HID * HID];
    __shared__ float sB[HID];
    int tid = threadIdx.x;
    for (int i = tid; i < HID * HID; i += blockDim.x) sW[i] = out_w[i];
    if (tid < HID) sB[tid] = out_b[tid];
    __syncthreads();

    int n = blockIdx.x * blockDim.x + tid;
    if (n >= n_nodes) return;

    g_deg[n] = 0;
    if (n == 0) g_total = 0;

    float x[HID];
#pragma unroll
    for (int k = 0; k < HID; k++) {
        float v = g_rst[n * HID + k];
        x[k] = v > 0.f ? v : expm1f(v);
    }
#pragma unroll
    for (int j = 0; j < HID; j++) {
        float a = sB[j];
#pragma unroll
        for (int k = 0; k < HID; k++) a += x[k] * sW[k * HID + j];
        out[n * HID + j] = a;
    }
}

// ============================================================================
extern "C" void kernel_launch(void* const* d_in, const int* in_sizes, int n_in,
                              void* d_out, int out_size) {
    const float* node_features = (const float*)d_in[0];
    const int*   src           = (const int*)  d_in[1];
    const int*   dst           = (const int*)  d_in[2];
    const float* lin0_w        = (const float*)d_in[3];
    const float* lin0_b        = (const float*)d_in[4];
    const float* fc_w          = (const float*)d_in[5];
    const float* attn_l        = (const float*)d_in[6];
    const float* attn_r        = (const float*)d_in[7];
    const float* gat_bias      = (const float*)d_in[8];
    const float* out_w         = (const float*)d_in[9];
    const float* out_b         = (const float*)d_in[10];

    int n  = in_sizes[0] / HID;
    int ne = in_sizes[1];

    int nb_np  = (n + 255) / 256;
    int nb_n   = (n + 127) / 128;
    int nb_s   = 148 * 4;
    int nb_g   = (n * 32 + 255) / 256;   // one warp per node

    prep0_hist<<<nb_np + nb_s, 256>>>(node_features, lin0_w, lin0_b,
                                      fc_w, attn_l, attn_r, gat_bias,
                                      dst, n, ne, nb_np);
    scan_fused<<<nb_np, 256>>>(n);
    scatter<<<nb_s, 256>>>(src, dst, ne);

    layer_edge<<<nb_g, 256>>>(n);        // launch 3 (profiled)

    for (int l = 1; l < 3; l++) {
        node_prep_mid<<<nb_n, 128>>>(fc_w + l * HID * HID,
                                     attn_l + l * HID, attn_r + l * HID,
                                     gat_bias + l * HID, n);
        layer_edge<<<nb_g, 256>>>(n);
    }
    out_proj<<<nb_n, 128>>>(out_w, out_b, (float*)d_out, n);
}